// round 3
// baseline (speedup 1.0000x reference)
#include <cuda_runtime.h>

// MakeCutouts: 64 cutouts of a [4,3,512,512] fp32 image, bilinear-resized to 224x224.
// Output [256,3,224,224] fp32, layout ((n*B+b)*C+c, i, j).
//
// One thread per (n,i,j). Coordinate math (floor/frac/clamp) is shared across the
// 12 (b,c) channels, so each thread does 48 gather loads + 12 coalesced stores.

#define IMG   512
#define S     224
#define CUTN  64
#define BB    4
#define CC    3
#define NCH   (BB*CC)        // 12 image planes
#define PLANE (IMG*IMG)      // 262144
#define OPLANE (S*S)         // 50176

__global__ __launch_bounds__(S, 4)
void make_cutouts_kernel(const float* __restrict__ x,
                         const int*   __restrict__ sizes,
                         const int*   __restrict__ offsetx,
                         const int*   __restrict__ offsety,
                         float*       __restrict__ out)
{
    const int j = threadIdx.x;     // output column
    const int i = blockIdx.x;      // output row
    const int n = blockIdx.y;      // cutout index

    const int   size  = sizes[n];
    const float sf    = (float)size;
    const float scale = sf * (1.0f / (float)S);
    const int   ox    = offsetx[n];
    const int   oy    = offsety[n];
    const int   sm1   = size - 1;

    // --- y (row) coordinate, same for all threads in block ---
    float srcy = fmaxf(scale * ((float)i + 0.5f) - 0.5f, 0.0f);
    int   iy0  = (int)floorf(srcy);
    float fy   = srcy - (float)iy0;
    iy0        = min(iy0, sm1);
    const int iy1 = min(iy0 + 1, sm1);

    // --- x (col) coordinate, per thread ---
    float srcx = fmaxf(scale * ((float)j + 0.5f) - 0.5f, 0.0f);
    int   ix0  = (int)floorf(srcx);
    float fx   = srcx - (float)ix0;
    ix0        = min(ix0, sm1);
    const int ix1 = min(ix0 + 1, sm1);

    const float wy1 = fy, wy0 = 1.0f - fy;
    const float wx1 = fx, wx0 = 1.0f - fx;
    const float w00 = wy0 * wx0;
    const float w01 = wy0 * wx1;
    const float w10 = wy1 * wx0;
    const float w11 = wy1 * wx1;

    const int r0 = (oy + iy0) * IMG;
    const int r1 = (oy + iy1) * IMG;
    const int c0 = ox + ix0;
    const int c1 = ox + ix1;

    const int p00 = r0 + c0;
    const int p01 = r0 + c1;
    const int p10 = r1 + c0;
    const int p11 = r1 + c1;

    int obase = (n * NCH) * OPLANE + i * S + j;

    #pragma unroll
    for (int bc = 0; bc < NCH; ++bc) {
        const float* __restrict__ xp = x + bc * PLANE;
        float v00 = __ldg(xp + p00);
        float v01 = __ldg(xp + p01);
        float v10 = __ldg(xp + p10);
        float v11 = __ldg(xp + p11);
        float r = v00 * w00;
        r = fmaf(v01, w01, r);
        r = fmaf(v10, w10, r);
        r = fmaf(v11, w11, r);
        out[obase] = r;
        obase += OPLANE;
    }
}

extern "C" void kernel_launch(void* const* d_in, const int* in_sizes, int n_in,
                              void* d_out, int out_size)
{
    const float* x       = (const float*)d_in[0];
    const int*   sizes   = (const int*)d_in[1];
    const int*   offsetx = (const int*)d_in[2];
    const int*   offsety = (const int*)d_in[3];
    // d_in[4] = cut_size scalar (compile-time constant S=224)
    float* out = (float*)d_out;

    dim3 grid(S, CUTN);
    dim3 block(S);
    make_cutouts_kernel<<<grid, block>>>(x, sizes, offsetx, offsety, out);
}

// round 4
// speedup vs baseline: 1.0268x; 1.0268x over previous
#include <cuda_runtime.h>

// MakeCutouts: 64 cutouts of [4,3,512,512] fp32, bilinear-resized to 224x224.
// Output [256,3,224,224] fp32.
//
// Flat 256-thread blocks: tid -> (n,i,j). Since 224 = 7*32 and 224*224 = 1568*32,
// every warp's 32 threads lie in one output row -> fully coalesced stores.
// Coordinate math amortized over the 12 (b,c) planes: 48 gathers + 12 stores/thread.
// Streaming stores (__stcs) keep the 12.6MB input L2-resident (64x reuse) instead
// of letting the 154MB output thrash L2.

#define IMG   512
#define S     224
#define CUTN  64
#define NCH   12             // B*C image planes
#define PLANE (IMG*IMG)      // 262144
#define OPLANE (S*S)         // 50176
#define TOTAL (CUTN*OPLANE)  // 3211264
#define TPB   256

__global__ __launch_bounds__(TPB, 4)
void make_cutouts_kernel(const float* __restrict__ x,
                         const int*   __restrict__ sizes,
                         const int*   __restrict__ offsetx,
                         const int*   __restrict__ offsety,
                         float*       __restrict__ out)
{
    const int g = blockIdx.x * TPB + threadIdx.x;   // grid sized exactly: no bounds check
    const int n   = g / OPLANE;
    const int rem = g - n * OPLANE;
    const int i   = rem / S;
    const int j   = rem - i * S;

    const int   size  = __ldg(sizes + n);
    const float scale = (float)size * (1.0f / (float)S);
    const int   ox    = __ldg(offsetx + n);
    const int   oy    = __ldg(offsety + n);
    const int   sm1   = size - 1;

    // y (row) source coordinate
    float srcy = fmaxf(scale * ((float)i + 0.5f) - 0.5f, 0.0f);
    int   iy0  = (int)floorf(srcy);
    float fy   = srcy - (float)iy0;
    iy0        = min(iy0, sm1);
    const int iy1 = min(iy0 + 1, sm1);

    // x (col) source coordinate
    float srcx = fmaxf(scale * ((float)j + 0.5f) - 0.5f, 0.0f);
    int   ix0  = (int)floorf(srcx);
    float fx   = srcx - (float)ix0;
    ix0        = min(ix0, sm1);
    const int ix1 = min(ix0 + 1, sm1);

    const float wy1 = fy, wy0 = 1.0f - fy;
    const float wx1 = fx, wx0 = 1.0f - fx;
    const float w00 = wy0 * wx0;
    const float w01 = wy0 * wx1;
    const float w10 = wy1 * wx0;
    const float w11 = wy1 * wx1;

    const int r0 = (oy + iy0) * IMG;
    const int r1 = (oy + iy1) * IMG;
    const int c0 = ox + ix0;
    const int c1 = ox + ix1;

    const int p00 = r0 + c0;
    const int p01 = r0 + c1;
    const int p10 = r1 + c0;
    const int p11 = r1 + c1;

    int obase = n * NCH * OPLANE + rem;   // (n, plane 0, i, j)

    #pragma unroll
    for (int bc = 0; bc < NCH; ++bc) {
        const float* __restrict__ xp = x + bc * PLANE;
        float v00 = __ldg(xp + p00);
        float v01 = __ldg(xp + p01);
        float v10 = __ldg(xp + p10);
        float v11 = __ldg(xp + p11);
        float r = v00 * w00;
        r = fmaf(v01, w01, r);
        r = fmaf(v10, w10, r);
        r = fmaf(v11, w11, r);
        __stcs(out + obase, r);          // streaming store: don't pollute L2
        obase += OPLANE;
    }
}

extern "C" void kernel_launch(void* const* d_in, const int* in_sizes, int n_in,
                              void* d_out, int out_size)
{
    const float* x       = (const float*)d_in[0];
    const int*   sizes   = (const int*)d_in[1];
    const int*   offsetx = (const int*)d_in[2];
    const int*   offsety = (const int*)d_in[3];
    float* out = (float*)d_out;

    make_cutouts_kernel<<<TOTAL / TPB, TPB>>>(x, sizes, offsetx, offsety, out);
}